// round 3
// baseline (speedup 1.0000x reference)
#include <cuda_runtime.h>
#include <cuda_bf16.h>
#include <math_constants.h>

// Problem constants
#define S_LEN 2048
#define B_SZ  64
#define D_SZ  1024

// GEMM tiling for v = h @ W  (v[b,n] = sum_e h[b,e] * W[e,n])
#define KSPLIT 16
#define KTILE  64   // D_SZ / KSPLIT
#define NTILE  64

// Scratch (device globals — no allocation allowed in kernel_launch)
__device__ float g_part[KSPLIT * B_SZ * D_SZ];   // 4 MB split-K partials
__device__ float g_v[B_SZ * D_SZ];               // 256 KB  v = h @ W
__device__ float g_energy[B_SZ * S_LEN];         // 512 KB  energies [B,S]

// ---------------------------------------------------------------------------
// Kernel 1: split-K GEMM partials.
// grid = (D/NTILE = 16, KSPLIT = 16), block = 256.
// Each block computes part[ks][b][nbase..nbase+63] over e in [ks*64, ks*64+64).
// ---------------------------------------------------------------------------
__global__ __launch_bounds__(256) void gemm_partial_kernel(
    const float* __restrict__ h,   // [B, D]
    const float* __restrict__ W)   // [D, D] row-major, W[e*D + n]
{
    __shared__ float hs[KTILE * B_SZ];   // hs[e*64 + b]   16 KB
    __shared__ float ws[KTILE * NTILE];  // ws[e*64 + n]   16 KB

    const int nt    = blockIdx.x;
    const int ks    = blockIdx.y;
    const int tid   = threadIdx.x;
    const int ebase = ks * KTILE;
    const int nbase = nt * NTILE;

    // Load h tile transposed: hs[e][b] = h[b*D + ebase + e]
    {
        const int b  = tid >> 2;            // 0..63
        const int e0 = (tid & 3) * 16;      // 0,16,32,48
        const float* hp = h + b * D_SZ + ebase + e0;
        #pragma unroll
        for (int i = 0; i < 16; i++) hs[(e0 + i) * 64 + b] = hp[i];
    }
    // Load W tile: ws[e][n] = W[(ebase+e)*D + nbase + n]
    {
        const int e  = tid >> 2;            // 0..63
        const int n0 = (tid & 3) * 16;      // 0,16,32,48
        const float* wp = W + (size_t)(ebase + e) * D_SZ + nbase + n0;
        #pragma unroll
        for (int i = 0; i < 16; i++) ws[e * 64 + n0 + i] = wp[i];
    }
    __syncthreads();

    // 4x4 register micro-tile per thread (64 b x 64 n across 256 threads)
    const int b0 = (tid >> 4) * 4;
    const int n0 = (tid & 15) * 4;
    float acc[4][4] = {};

    #pragma unroll 8
    for (int e = 0; e < KTILE; e++) {
        const float4 hv = *(const float4*)(hs + e * 64 + b0);
        const float4 wv = *(const float4*)(ws + e * 64 + n0);
        acc[0][0] = fmaf(hv.x, wv.x, acc[0][0]);
        acc[0][1] = fmaf(hv.x, wv.y, acc[0][1]);
        acc[0][2] = fmaf(hv.x, wv.z, acc[0][2]);
        acc[0][3] = fmaf(hv.x, wv.w, acc[0][3]);
        acc[1][0] = fmaf(hv.y, wv.x, acc[1][0]);
        acc[1][1] = fmaf(hv.y, wv.y, acc[1][1]);
        acc[1][2] = fmaf(hv.y, wv.z, acc[1][2]);
        acc[1][3] = fmaf(hv.y, wv.w, acc[1][3]);
        acc[2][0] = fmaf(hv.z, wv.x, acc[2][0]);
        acc[2][1] = fmaf(hv.z, wv.y, acc[2][1]);
        acc[2][2] = fmaf(hv.z, wv.z, acc[2][2]);
        acc[2][3] = fmaf(hv.z, wv.w, acc[2][3]);
        acc[3][0] = fmaf(hv.w, wv.x, acc[3][0]);
        acc[3][1] = fmaf(hv.w, wv.y, acc[3][1]);
        acc[3][2] = fmaf(hv.w, wv.z, acc[3][2]);
        acc[3][3] = fmaf(hv.w, wv.w, acc[3][3]);
    }

    float* outp = g_part + (size_t)ks * (B_SZ * D_SZ);
    #pragma unroll
    for (int i = 0; i < 4; i++) {
        float4 r = make_float4(acc[i][0], acc[i][1], acc[i][2], acc[i][3]);
        *(float4*)(outp + (b0 + i) * D_SZ + nbase + n0) = r;
    }
}

// ---------------------------------------------------------------------------
// Kernel 2: reduce split-K partials into g_v. grid = 256, block = 256.
// ---------------------------------------------------------------------------
__global__ __launch_bounds__(256) void reduce_v_kernel() {
    const int idx = blockIdx.x * 256 + threadIdx.x;   // 0 .. B*D-1
    float s = 0.f;
    #pragma unroll
    for (int k = 0; k < KSPLIT; k++)
        s += g_part[(size_t)k * (B_SZ * D_SZ) + idx];
    g_v[idx] = s;
}

// ---------------------------------------------------------------------------
// Kernel 3: energies[b,s] = v[b] . enc[s,b].  THE memory-bound pass (512 MB).
// grid = (S/64 = 32, B = 64), block = 256 (8 warps). Warp per (s,b) row:
// 8 x float4 per lane, fully coalesced 4KB contiguous rows.
// ---------------------------------------------------------------------------
__global__ __launch_bounds__(256) void energy_kernel(const float* __restrict__ enc) {
    __shared__ float vs[D_SZ];   // v[b], 4 KB

    const int b     = blockIdx.y;
    const int sbase = blockIdx.x * 64;
    const int tid   = threadIdx.x;

    *(float4*)(vs + tid * 4) = *(const float4*)(g_v + b * D_SZ + tid * 4);
    __syncthreads();

    const int warp = tid >> 5;
    const int lane = tid & 31;

    #pragma unroll
    for (int si = 0; si < 8; si++) {
        const int s = sbase + warp + si * 8;
        const float4* ep =
            reinterpret_cast<const float4*>(enc + ((size_t)s * B_SZ + b) * D_SZ) + lane;
        float sum = 0.f;
        #pragma unroll
        for (int i = 0; i < 8; i++) {
            const float4 e4 = ep[i * 32];
            const float4 v4 = *(const float4*)(vs + i * 128 + lane * 4);
            sum = fmaf(e4.x, v4.x, sum);
            sum = fmaf(e4.y, v4.y, sum);
            sum = fmaf(e4.z, v4.z, sum);
            sum = fmaf(e4.w, v4.w, sum);
        }
        #pragma unroll
        for (int o = 16; o; o >>= 1) sum += __shfl_xor_sync(0xffffffffu, sum, o);
        if (lane == 0) g_energy[b * S_LEN + s] = sum;
    }
}

// ---------------------------------------------------------------------------
// Kernel 4: row softmax over S. grid = B, block = 256, 8 elems/thread.
// out shape [B,1,S] contiguous.
// ---------------------------------------------------------------------------
__global__ __launch_bounds__(256) void softmax_kernel(float* __restrict__ out) {
    __shared__ float red[8];
    const int b    = blockIdx.x;
    const int tid  = threadIdx.x;
    const int warp = tid >> 5;
    const int lane = tid & 31;
    const float* e = g_energy + b * S_LEN;

    float vals[8];
    float m = -CUDART_INF_F;
    #pragma unroll
    for (int i = 0; i < 8; i++) {
        vals[i] = e[i * 256 + tid];
        m = fmaxf(m, vals[i]);
    }
    #pragma unroll
    for (int o = 16; o; o >>= 1) m = fmaxf(m, __shfl_xor_sync(0xffffffffu, m, o));
    if (lane == 0) red[warp] = m;
    __syncthreads();
    float bm = red[0];
    #pragma unroll
    for (int i = 1; i < 8; i++) bm = fmaxf(bm, red[i]);
    __syncthreads();

    float sum = 0.f;
    #pragma unroll
    for (int i = 0; i < 8; i++) {
        vals[i] = expf(vals[i] - bm);
        sum += vals[i];
    }
    #pragma unroll
    for (int o = 16; o; o >>= 1) sum += __shfl_xor_sync(0xffffffffu, sum, o);
    if (lane == 0) red[warp] = sum;
    __syncthreads();
    float tot = 0.f;
    #pragma unroll
    for (int i = 0; i < 8; i++) tot += red[i];
    const float inv = 1.0f / tot;

    #pragma unroll
    for (int i = 0; i < 8; i++)
        out[b * S_LEN + i * 256 + tid] = vals[i] * inv;
}

// ---------------------------------------------------------------------------
// Launch. Inputs per metadata order: hidden [1,B,D], encoder_outputs [S,B,D],
// W_attn [D,D], b_attn [D] (b_attn cancels in softmax -> unused).
// ---------------------------------------------------------------------------
extern "C" void kernel_launch(void* const* d_in, const int* in_sizes, int n_in,
                              void* d_out, int out_size) {
    const float* hidden = (const float*)d_in[0];
    const float* enc    = (const float*)d_in[1];
    const float* W      = (const float*)d_in[2];
    float* out          = (float*)d_out;

    gemm_partial_kernel<<<dim3(D_SZ / NTILE, KSPLIT), 256>>>(hidden, W);
    reduce_v_kernel<<<(B_SZ * D_SZ) / 256, 256>>>();
    energy_kernel<<<dim3(S_LEN / 64, B_SZ), 256>>>(enc);
    softmax_kernel<<<B_SZ, 256>>>(out);
}

// round 4
// speedup vs baseline: 1.0417x; 1.0417x over previous
#include <cuda_runtime.h>
#include <cuda_bf16.h>
#include <math_constants.h>

// Problem constants
#define S_LEN 2048
#define B_SZ  64
#define D_SZ  1024

// GEMM tiling for v = h @ W  (v[b,n] = sum_e h[b,e] * W[e,n])
#define KSPLIT 16
#define KTILE  64   // D_SZ / KSPLIT
#define NTILE  64

// Scratch (device globals — no allocation allowed in kernel_launch)
__device__ float g_part[KSPLIT * B_SZ * D_SZ];   // 4 MB split-K partials
__device__ float g_v[B_SZ * D_SZ];               // 256 KB  v = h @ W
__device__ float g_energy[B_SZ * S_LEN];         // 512 KB  energies [B,S]

// ---------------------------------------------------------------------------
// Kernel 1: split-K GEMM partials.
// grid = (D/NTILE = 16, KSPLIT = 16), block = 256.
// ---------------------------------------------------------------------------
__global__ __launch_bounds__(256) void gemm_partial_kernel(
    const float* __restrict__ h,   // [B, D]
    const float* __restrict__ W)   // [D, D] row-major, W[e*D + n]
{
    __shared__ float hs[KTILE * B_SZ];   // hs[e*64 + b]
    __shared__ float ws[KTILE * NTILE];  // ws[e*64 + n]

    const int nt    = blockIdx.x;
    const int ks    = blockIdx.y;
    const int tid   = threadIdx.x;
    const int ebase = ks * KTILE;
    const int nbase = nt * NTILE;

    {
        const int b  = tid >> 2;
        const int e0 = (tid & 3) * 16;
        const float* hp = h + b * D_SZ + ebase + e0;
        #pragma unroll
        for (int i = 0; i < 16; i++) hs[(e0 + i) * 64 + b] = hp[i];
    }
    {
        const int e  = tid >> 2;
        const int n0 = (tid & 3) * 16;
        const float* wp = W + (size_t)(ebase + e) * D_SZ + nbase + n0;
        #pragma unroll
        for (int i = 0; i < 16; i++) ws[e * 64 + n0 + i] = wp[i];
    }
    __syncthreads();

    const int b0 = (tid >> 4) * 4;
    const int n0 = (tid & 15) * 4;
    float acc[4][4] = {};

    #pragma unroll 8
    for (int e = 0; e < KTILE; e++) {
        const float4 hv = *(const float4*)(hs + e * 64 + b0);
        const float4 wv = *(const float4*)(ws + e * 64 + n0);
        acc[0][0] = fmaf(hv.x, wv.x, acc[0][0]);
        acc[0][1] = fmaf(hv.x, wv.y, acc[0][1]);
        acc[0][2] = fmaf(hv.x, wv.z, acc[0][2]);
        acc[0][3] = fmaf(hv.x, wv.w, acc[0][3]);
        acc[1][0] = fmaf(hv.y, wv.x, acc[1][0]);
        acc[1][1] = fmaf(hv.y, wv.y, acc[1][1]);
        acc[1][2] = fmaf(hv.y, wv.z, acc[1][2]);
        acc[1][3] = fmaf(hv.y, wv.w, acc[1][3]);
        acc[2][0] = fmaf(hv.z, wv.x, acc[2][0]);
        acc[2][1] = fmaf(hv.z, wv.y, acc[2][1]);
        acc[2][2] = fmaf(hv.z, wv.z, acc[2][2]);
        acc[2][3] = fmaf(hv.z, wv.w, acc[2][3]);
        acc[3][0] = fmaf(hv.w, wv.x, acc[3][0]);
        acc[3][1] = fmaf(hv.w, wv.y, acc[3][1]);
        acc[3][2] = fmaf(hv.w, wv.z, acc[3][2]);
        acc[3][3] = fmaf(hv.w, wv.w, acc[3][3]);
    }

    float* outp = g_part + (size_t)ks * (B_SZ * D_SZ);
    #pragma unroll
    for (int i = 0; i < 4; i++) {
        float4 r = make_float4(acc[i][0], acc[i][1], acc[i][2], acc[i][3]);
        *(float4*)(outp + (b0 + i) * D_SZ + nbase + n0) = r;
    }
}

// ---------------------------------------------------------------------------
// Kernel 2: reduce split-K partials into g_v, float4-vectorized.
// grid = (B*D/4)/256 = 64, block = 256. 16 independent float4 loads/thread.
// ---------------------------------------------------------------------------
__global__ __launch_bounds__(256) void reduce_v_kernel() {
    const int idx4 = blockIdx.x * 256 + threadIdx.x;   // 0 .. B*D/4-1
    float4 s = make_float4(0.f, 0.f, 0.f, 0.f);
    #pragma unroll
    for (int k = 0; k < KSPLIT; k++) {
        const float4 p = *((const float4*)g_part + (size_t)k * (B_SZ * D_SZ / 4) + idx4);
        s.x += p.x; s.y += p.y; s.z += p.z; s.w += p.w;
    }
    *((float4*)g_v + idx4) = s;
}

// ---------------------------------------------------------------------------
// Kernel 3: energies[b,s] = v[b] . enc[s,b].  THE memory-bound pass (512 MB).
// grid = (S/8 = 256, B/8 = 8), block = 256 (8 warps).
// Block tile = 8 s x 8 b: warps within a block read ADJACENT b rows, so per s
// the block touches a contiguous 32KB span (DRAM page locality). Each lane
// issues 8 independent float4 __ldcs loads per row (evict-first: zero reuse).
// ---------------------------------------------------------------------------
__global__ __launch_bounds__(256) void energy_kernel(const float* __restrict__ enc) {
    __shared__ float vs[8][D_SZ];   // v for 8 b's, 32 KB

    const int bbase = blockIdx.y * 8;
    const int sbase = blockIdx.x * 8;
    const int tid   = threadIdx.x;

    // Load 8 x 4KB of v: 8 float4 per thread
    {
        const float4* src = (const float4*)(g_v + bbase * D_SZ);
        float4* dst = (float4*)&vs[0][0];
        #pragma unroll
        for (int i = 0; i < 8; i++) dst[tid + i * 256] = src[tid + i * 256];
    }
    __syncthreads();

    const int warp = tid >> 5;
    const int lane = tid & 31;
    const int b    = bbase + warp;
    const float* vp = vs[warp];

    #pragma unroll
    for (int si = 0; si < 8; si++) {
        const int s = sbase + si;
        const float4* ep =
            reinterpret_cast<const float4*>(enc + ((size_t)s * B_SZ + b) * D_SZ) + lane;
        float sum = 0.f;
        #pragma unroll
        for (int i = 0; i < 8; i++) {
            const float4 e4 = __ldcs(ep + i * 32);
            const float4 v4 = *(const float4*)(vp + i * 128 + lane * 4);
            sum = fmaf(e4.x, v4.x, sum);
            sum = fmaf(e4.y, v4.y, sum);
            sum = fmaf(e4.z, v4.z, sum);
            sum = fmaf(e4.w, v4.w, sum);
        }
        #pragma unroll
        for (int o = 16; o; o >>= 1) sum += __shfl_xor_sync(0xffffffffu, sum, o);
        if (lane == 0) g_energy[b * S_LEN + s] = sum;
    }
}

// ---------------------------------------------------------------------------
// Kernel 4: row softmax over S. grid = B, block = 1024, 2 elems/thread.
// out shape [B,1,S] contiguous.
// ---------------------------------------------------------------------------
__global__ __launch_bounds__(1024) void softmax_kernel(float* __restrict__ out) {
    __shared__ float red[32];
    __shared__ float bcast[2];
    const int b    = blockIdx.x;
    const int tid  = threadIdx.x;
    const int warp = tid >> 5;
    const int lane = tid & 31;
    const float* e = g_energy + b * S_LEN;

    float v0 = e[tid];
    float v1 = e[tid + 1024];

    // block max
    float m = fmaxf(v0, v1);
    #pragma unroll
    for (int o = 16; o; o >>= 1) m = fmaxf(m, __shfl_xor_sync(0xffffffffu, m, o));
    if (lane == 0) red[warp] = m;
    __syncthreads();
    if (warp == 0) {
        float t = red[lane];
        #pragma unroll
        for (int o = 16; o; o >>= 1) t = fmaxf(t, __shfl_xor_sync(0xffffffffu, t, o));
        if (lane == 0) bcast[0] = t;
    }
    __syncthreads();
    const float bm = bcast[0];

    // block sum of exp
    v0 = __expf(v0 - bm);
    v1 = __expf(v1 - bm);
    float s = v0 + v1;
    #pragma unroll
    for (int o = 16; o; o >>= 1) s += __shfl_xor_sync(0xffffffffu, s, o);
    if (lane == 0) red[warp] = s;
    __syncthreads();
    if (warp == 0) {
        float t = red[lane];
        #pragma unroll
        for (int o = 16; o; o >>= 1) t += __shfl_xor_sync(0xffffffffu, t, o);
        if (lane == 0) bcast[1] = t;
    }
    __syncthreads();
    const float inv = 1.0f / bcast[1];

    out[b * S_LEN + tid]        = v0 * inv;
    out[b * S_LEN + tid + 1024] = v1 * inv;
}

// ---------------------------------------------------------------------------
// Launch. Inputs: hidden [1,B,D], encoder_outputs [S,B,D], W_attn [D,D],
// b_attn [D] (cancels in softmax -> unused).
// ---------------------------------------------------------------------------
extern "C" void kernel_launch(void* const* d_in, const int* in_sizes, int n_in,
                              void* d_out, int out_size) {
    const float* hidden = (const float*)d_in[0];
    const float* enc    = (const float*)d_in[1];
    const float* W      = (const float*)d_in[2];
    float* out          = (float*)d_out;

    gemm_partial_kernel<<<dim3(D_SZ / NTILE, KSPLIT), 256>>>(hidden, W);
    reduce_v_kernel<<<(B_SZ * D_SZ / 4) / 256, 256>>>();
    energy_kernel<<<dim3(S_LEN / 8, B_SZ / 8), 256>>>(enc);
    softmax_kernel<<<B_SZ, 1024>>>(out);
}